// round 16
// baseline (speedup 1.0000x reference)
#include <cuda_runtime.h>
#include <cstddef>

typedef unsigned long long u64;

__device__ __forceinline__ u64 pk2(float lo, float hi) {
    u64 r; asm("mov.b64 %0,{%1,%2};" : "=l"(r) : "f"(lo), "f"(hi)); return r;
}
__device__ __forceinline__ void upk2(u64 v, float& lo, float& hi) {
    asm("mov.b64 {%0,%1},%2;" : "=f"(lo), "=f"(hi) : "l"(v));
}
__device__ __forceinline__ void fma2(u64& d, u64 a, u64 b) {
    asm("fma.rn.f32x2 %0,%1,%2,%0;" : "+l"(d) : "l"(a), "l"(b));
}

// B=256, L=64, D=1024
// left'[k,d] = sum_l Wl[k,l]*left[l,d] + bl[k]   (same right)
// corr[i,d]  = sum_j left'[j,d]*right'[j+63-i,d] (i in [0,128), row 127 = 0)
// y[k,d]     = sum_c sum_t Wconv[k,c,t]*corr[c,d+t-1]  (zero pad in d)

namespace {
constexpr int Dc  = 1024;
constexpr int ST  = 68;                          // row stride everywhere (17 u64-pairs)
constexpr int OFF_A = 0;                         // A = left': 64 rows, col c at offset c
constexpr int OFF_B = 64 * ST;                   // B: 79 local rows = orig rows 56..134
constexpr int OFF_C = OFF_B + 79 * ST;           // 9724: W^T (ph0/1) -> corr 128 rows
constexpr int WT_SZ = 64 * ST;                   // 4352 per mat
constexpr int OFF_H = OFF_C + 128 * ST;          // halo raw scratch 128 u64
constexpr int SMEM_FLOATS = OFF_H + 256;         // 18684 fl = 74736 B -> 3 CTAs/SM
constexpr int SMEM_BYTES  = SMEM_FLOATS * 4;
constexpr int U64_B = OFF_B / 2;                 // 2176
constexpr int U64_C = OFF_C / 2;                 // 4862
constexpr int U64_H = OFF_H / 2;
}

__global__ void __launch_bounds__(256, 3)
cc_fused_kernel(const float* __restrict__ left,  const float* __restrict__ right,
                const float* __restrict__ Wl,    const float* __restrict__ bl,
                const float* __restrict__ Wr,    const float* __restrict__ br,
                const float* __restrict__ Wconv, float* __restrict__ out)
{
    extern __shared__ float sm[];
    const int tid = threadIdx.x;
    const int b   = blockIdx.y;
    const int dg0 = blockIdx.x * 64;    // global d of tile col 1 (col 0 = d-1 halo)
    const float* Lb = left  + (size_t)b * 65536;
    const float* Rb = right + (size_t)b * 65536;

    // ---- phase 0: W^T, halo raw scratch, zero B pad rows ----
    for (int i = tid; i < 8192; i += 256) {      // W^T[l][k], stride 68, in C region
        int which = i >> 12, r = i & 4095;
        int k = r >> 6, l = r & 63;
        sm[OFF_C + which * WT_SZ + l * ST + k] = (which ? Wr : Wl)[r];
    }
    if (tid < 128) {                             // H[mat*64+l] = {raw[l][dg0-1], raw[l][dg0+64]}
        int mat = tid >> 6, l = tid & 63;
        const float* src = (mat ? Rb : Lb) + l * 1024;
        float f0 = dg0 ? __ldg(src + dg0 - 1) : 0.f;
        float f1 = (dg0 != 960) ? __ldg(src + dg0 + 64) : 0.f;
        reinterpret_cast<u64*>(sm)[U64_H + tid] = pk2(f0, f1);
    }
    {
        u64* zb = reinterpret_cast<u64*>(sm) + U64_B;
        for (int i = tid; i < 510; i += 256) {   // pad rows local 0..7, 72..78
            int r = i / 34, c = i % 34;
            int row = (r < 8) ? r : (64 + r);
            zb[row * 34 + c] = 0ull;
        }
    }
    __syncthreads();

    // ---- phase 1: linears, raw streamed from global, outputs to smem ----
    {
        const int w    = tid >> 5, lane = tid & 31;
        const int mat  = w >> 2;                 // 0: left, 1: right
        const int kq   = w & 3,  k0 = kq * 16;
        const float* bias = mat ? br : bl;
        const float* rsrc = (mat ? Rb : Lb) + dg0 + 2 * lane;   // 8B-aligned pairs
        const ulonglong2* wt2 = reinterpret_cast<const ulonglong2*>(sm + OFF_C + mat * WT_SZ);

        u64 acc[8][2];
        #pragma unroll
        for (int kp = 0; kp < 8; ++kp) {
            u64 bp_ = pk2(__ldg(bias + k0 + 2 * kp), __ldg(bias + k0 + 2 * kp + 1));
            acc[kp][0] = bp_; acc[kp][1] = bp_;
        }
        #pragma unroll 4
        for (int l = 0; l < 64; ++l) {
            float2 rv = __ldg(reinterpret_cast<const float2*>(rsrc + l * 1024));
            u64 p0 = pk2(rv.x, rv.x), p1 = pk2(rv.y, rv.y);
            const ulonglong2* wl_ = wt2 + l * 17 + 4 * kq;
            #pragma unroll
            for (int i = 0; i < 4; ++i) {
                ulonglong2 ww = wl_[i];          // broadcast LDS.128 = 2 k-pairs
                fma2(acc[2 * i][0],     ww.x, p0);
                fma2(acc[2 * i][1],     ww.x, p1);
                fma2(acc[2 * i + 1][0], ww.y, p0);
                fma2(acc[2 * i + 1][1], ww.y, p1);
            }
        }
        // thread owns tile cols (2lane+1, 2lane+2)
        float* ost = sm + (mat ? (OFF_B + 8 * ST) : OFF_A) + 2 * lane + 1;
        #pragma unroll
        for (int kp = 0; kp < 8; ++kp) {
            float a0, b0_, a1, b1_;
            upk2(acc[kp][0], a0, b0_);           // col 2lane+1: k even, k odd
            upk2(acc[kp][1], a1, b1_);           // col 2lane+2
            ost[(k0 + 2 * kp) * ST + 0]     = a0;
            ost[(k0 + 2 * kp) * ST + 1]     = a1;
            ost[(k0 + 2 * kp + 1) * ST + 0] = b0_;
            ost[(k0 + 2 * kp + 1) * ST + 1] = b1_;
        }

        // tail cols (0,65) via H scratch: 2 mats x 64 k x 2 l-halves
        const int hmat = tid >> 7;
        const int hk   = (tid >> 1) & 63;
        const int lh   = tid & 1;
        const u64* Hp = reinterpret_cast<const u64*>(sm) + U64_H + hmat * 64;
        const float* wt = sm + OFF_C + hmat * WT_SZ + hk;
        const float* bias2 = hmat ? br : bl;
        u64 hacc = lh ? 0ull : pk2(__ldg(bias2 + hk), __ldg(bias2 + hk));
        #pragma unroll 8
        for (int t = 0; t < 32; ++t) {
            int l = 32 * lh + t;
            float wv = wt[l * ST];
            fma2(hacc, pk2(wv, wv), Hp[l]);      // lo: col0, hi: col65
        }
        float alo, ahi; upk2(hacc, alo, ahi);
        alo += __shfl_xor_sync(0xFFFFFFFFu, alo, 1);
        ahi += __shfl_xor_sync(0xFFFFFFFFu, ahi, 1);
        if (!lh) {
            float* tb = sm + (hmat ? (OFF_B + 8 * ST) : OFF_A) + hk * ST;
            tb[0]  = alo;
            tb[65] = ahi;
        }
    }
    __syncthreads();

    // ---- phase 2: correlation, 16-deep window, one 16-i block per warp ----
    {
        const int cp = tid & 31;                  // col pair (2cp, 2cp+1)
        const int i0 = 16 * (tid >> 5);           // warp's i-block [i0, i0+16)
        const bool lower = (i0 < 64);
        const int jlo = lower ? 0 : (i0 - 64);    // dense start (padded to x8 via zero rows)
        const int nch = lower ? (i0 / 8 + 1) : ((128 - i0) / 8);
        const u64* ap = reinterpret_cast<const u64*>(sm) + cp;           // A row j at j*34
        const u64* bp = reinterpret_cast<const u64*>(sm) + U64_B + cp;   // local row r at r*34
        u64* cst = reinterpret_cast<u64*>(sm) + U64_C + cp;
        const u64 keep = (dg0 == 0 && cp == 0) ? 0xFFFFFFFF00000000ull : ~0ull;

        u64 acc[16], win[16];
        #pragma unroll
        for (int q = 0; q < 16; ++q) acc[q] = 0ull;
        const int pre = lower ? (71 - i0) : 7;    // preload base index
        #pragma unroll
        for (int q = 1; q < 16; ++q) {
            int idx = pre - q;
            win[q] = (idx >= 0) ? bp[idx * 34] : 0ull;
        }
        const u64* ap2 = ap + jlo * 34;
        const u64* bp2 = bp + (jlo + 71 - i0) * 34;
        #pragma unroll 1
        for (int ch = 0; ch < nch; ++ch) {
            #pragma unroll
            for (int t = 0; t < 8; ++t) {
                const int jj = 8 * ch + t;
                u64 av = ap2[jj * 34];
                u64 nv = bp2[jj * 34];
                fma2(acc[0], av, nv);
                #pragma unroll
                for (int q = 1; q < 16; ++q) fma2(acc[q], av, win[q]);
                #pragma unroll
                for (int q = 15; q > 1; --q) win[q] = win[q - 1];
                win[1] = nv;
            }
        }
        if (lower) {                              // drain: 8 steps, zeros shift in
            #pragma unroll
            for (int t = 0; t < 8; ++t) {
                u64 av = ap[(i0 + 8 + t) * 34];
                #pragma unroll
                for (int q = 1; q < 16; ++q) fma2(acc[q], av, win[q]);
                #pragma unroll
                for (int q = 15; q > 1; --q) win[q] = win[q - 1];
                win[1] = 0ull;
            }
        }
        #pragma unroll
        for (int q = 0; q < 16; ++q) cst[(i0 + q) * 34] = acc[q] & keep;

        // tail cols (64,65): windowed j-range, stride-2 split per thread pair
        const int hi = tid >> 1;
        const int jh = tid & 1;
        const int tjlo = (hi > 63) ? (hi - 63) : 0;
        const int tjhi = (hi < 63) ? hi : 63;
        const u64* a2p = reinterpret_cast<const u64*>(sm) + 32;          // A halo word
        const u64* b2p = reinterpret_cast<const u64*>(sm) + U64_B + 32;  // B halo word
        u64 hacc = 0ull;
        #pragma unroll 4
        for (int j = tjlo + jh; j <= tjhi; j += 2)
            fma2(hacc, a2p[j * 34], b2p[(j + 71 - hi) * 34]);
        float alo, ahi; upk2(hacc, alo, ahi);
        alo += __shfl_xor_sync(0xFFFFFFFFu, alo, 1);
        ahi += __shfl_xor_sync(0xFFFFFFFFu, ahi, 1);
        if (!jh) {
            u64 v = pk2(alo, ahi);
            if (dg0 == 960) v &= 0x00000000FFFFFFFFull;   // col 65 = d 1024 invalid
            reinterpret_cast<u64*>(sm)[U64_C + hi * 34 + 32] = v;
        }
    }

    // ---- phase 3: conv(128->64,k=3), 4d x 4k, warp spans 8 dq (halved d-span) ----
    const int w3 = tid >> 5, ln3 = tid & 31;
    const int dq = ((w3 & 1) << 3) | (ln3 & 7);   // 0..15
    const int kq = ((w3 >> 1) << 2) | (ln3 >> 3); // 0..15
    const int d0 = 4 * dq;
    u64 acc3[2][4];
    #pragma unroll
    for (int p = 0; p < 2; ++p)
        #pragma unroll
        for (int dd = 0; dd < 4; ++dd) acc3[p][dd] = 0ull;

    ulonglong2* wAs = reinterpret_cast<ulonglong2*>(sm);        // A region (dead)
    u64*        wBs = reinterpret_cast<u64*>(sm) + U64_B;       // B region (dead)
    #pragma unroll 1
    for (int s = 0; s < 4; ++s) {
        __syncthreads();   // corr written (s=0) / prev-stage weight reads done
        for (int i = tid; i < 1024; i += 256) {
            int kp = i >> 5, cl = i & 31;
            const float* s0 = Wconv + (2 * kp) * 384 + (32 * s + cl) * 3;
            ulonglong2 v;
            v.x = pk2(__ldg(s0 + 0), __ldg(s0 + 384));
            v.y = pk2(__ldg(s0 + 1), __ldg(s0 + 385));
            wAs[kp * 33 + cl] = v;
            wBs[kp * 33 + cl] = pk2(__ldg(s0 + 2), __ldg(s0 + 386));
        }
        __syncthreads();
        const float* cb = sm + OFF_C + (32 * s) * ST + d0;
        #pragma unroll 4
        for (int cl = 0; cl < 32; ++cl) {
            const float* crow = cb + cl * ST;
            ulonglong2 cA = *reinterpret_cast<const ulonglong2*>(crow);  // d0..d0+3
            float2     cC = *reinterpret_cast<const float2*>(crow + 4);  // d0+4, d0+5
            float f0, f1, f2, f3;
            upk2(cA.x, f0, f1); upk2(cA.y, f2, f3);
            u64 cv[6] = { pk2(f0, f0), pk2(f1, f1), pk2(f2, f2),
                          pk2(f3, f3), pk2(cC.x, cC.x), pk2(cC.y, cC.y) };
            #pragma unroll
            for (int p = 0; p < 2; ++p) {
                ulonglong2 wa = wAs[(2 * kq + p) * 33 + cl];
                u64        wb = wBs[(2 * kq + p) * 33 + cl];
                #pragma unroll
                for (int dd = 0; dd < 4; ++dd) {
                    fma2(acc3[p][dd], wa.x, cv[dd]);
                    fma2(acc3[p][dd], wa.y, cv[dd + 1]);
                    fma2(acc3[p][dd], wb,   cv[dd + 2]);
                }
            }
        }
    }

    float* ob = out + (size_t)b * 65536 + dg0 + d0;
    #pragma unroll
    for (int p = 0; p < 2; ++p) {
        float lo[4], hi[4];
        #pragma unroll
        for (int dd = 0; dd < 4; ++dd) upk2(acc3[p][dd], lo[dd], hi[dd]);
        float* o0 = ob + (size_t)(4 * kq + 2 * p) * Dc;
        *reinterpret_cast<float4*>(o0)      = make_float4(lo[0], lo[1], lo[2], lo[3]);
        *reinterpret_cast<float4*>(o0 + Dc) = make_float4(hi[0], hi[1], hi[2], hi[3]);
    }
}

extern "C" void kernel_launch(void* const* d_in, const int* in_sizes, int n_in,
                              void* d_out, int out_size)
{
    (void)in_sizes; (void)n_in; (void)out_size;
    const float* left  = (const float*)d_in[0];
    const float* right = (const float*)d_in[1];
    const float* Wl    = (const float*)d_in[2];
    const float* bl    = (const float*)d_in[3];
    const float* Wr    = (const float*)d_in[4];
    const float* br    = (const float*)d_in[5];
    const float* Wconv = (const float*)d_in[6];
    float* out = (float*)d_out;

    cudaFuncSetAttribute(cc_fused_kernel,
                         cudaFuncAttributeMaxDynamicSharedMemorySize, SMEM_BYTES);
    dim3 grid(Dc / 64, 256, 1);   // 4096 CTAs: one batch x 64-wide d-tile
    cc_fused_kernel<<<grid, 256, SMEM_BYTES>>>(left, right, Wl, bl, Wr, br, Wconv, out);
}

// round 17
// speedup vs baseline: 1.0553x; 1.0553x over previous
#include <cuda_runtime.h>
#include <cstddef>

typedef unsigned long long u64;

__device__ __forceinline__ u64 pk2(float lo, float hi) {
    u64 r; asm("mov.b64 %0,{%1,%2};" : "=l"(r) : "f"(lo), "f"(hi)); return r;
}
__device__ __forceinline__ void upk2(u64 v, float& lo, float& hi) {
    asm("mov.b64 {%0,%1},%2;" : "=f"(lo), "=f"(hi) : "l"(v));
}
__device__ __forceinline__ void fma2(u64& d, u64 a, u64 b) {
    asm("fma.rn.f32x2 %0,%1,%2,%0;" : "+l"(d) : "l"(a), "l"(b));
}

// B=256, L=64, D=1024
// left'[k,d] = sum_l Wl[k,l]*left[l,d] + bl[k]   (same right)
// corr[i,d]  = sum_j left'[j,d]*right'[j+63-i,d] (i in [0,128), row 127 = 0)
// y[k,d]     = sum_c sum_t Wconv[k,c,t]*corr[c,d+t-1]  (zero pad in d)

namespace {
constexpr int Dc  = 1024;
constexpr int ST  = 68;                          // row stride everywhere (17 u64-pairs)
constexpr int OFF_A = 0;                         // A = left': 64 rows, col c at offset c
constexpr int OFF_B = 64 * ST;                   // B: 79 local rows = orig rows 56..134
constexpr int OFF_C = OFF_B + 79 * ST;           // 9724: W^T (ph0/1) -> corr 128 rows
constexpr int WT_SZ = 64 * ST;                   // 4352 per mat
constexpr int OFF_H = OFF_C + 128 * ST;          // halo raw scratch 128 u64
constexpr int SMEM_FLOATS = OFF_H + 256;         // 18684 fl = 74736 B -> 3 CTAs/SM
constexpr int SMEM_BYTES  = SMEM_FLOATS * 4;
constexpr int U64_B = OFF_B / 2;                 // 2176
constexpr int U64_C = OFF_C / 2;                 // 4862
constexpr int U64_H = OFF_H / 2;
}

__global__ void __launch_bounds__(256, 3)
cc_fused_kernel(const float* __restrict__ left,  const float* __restrict__ right,
                const float* __restrict__ Wl,    const float* __restrict__ bl,
                const float* __restrict__ Wr,    const float* __restrict__ br,
                const float* __restrict__ Wconv, float* __restrict__ out)
{
    extern __shared__ float sm[];
    const int tid = threadIdx.x;
    const int b   = blockIdx.y;
    const int dg0 = blockIdx.x * 64;    // global d of tile col 1 (col 0 = d-1 halo)
    const float* Lb = left  + (size_t)b * 65536;
    const float* Rb = right + (size_t)b * 65536;

    // ---- phase 0: W^T, halo raw scratch, zero B pad rows ----
    for (int i = tid; i < 8192; i += 256) {      // W^T[l][k], stride 68, in C region
        int which = i >> 12, r = i & 4095;
        int k = r >> 6, l = r & 63;
        sm[OFF_C + which * WT_SZ + l * ST + k] = (which ? Wr : Wl)[r];
    }
    if (tid < 128) {                             // H[mat*64+l] = {raw[l][dg0-1], raw[l][dg0+64]}
        int mat = tid >> 6, l = tid & 63;
        const float* src = (mat ? Rb : Lb) + l * 1024;
        float f0 = dg0 ? __ldg(src + dg0 - 1) : 0.f;
        float f1 = (dg0 != 960) ? __ldg(src + dg0 + 64) : 0.f;
        reinterpret_cast<u64*>(sm)[U64_H + tid] = pk2(f0, f1);
    }
    {
        u64* zb = reinterpret_cast<u64*>(sm) + U64_B;
        for (int i = tid; i < 510; i += 256) {   // pad rows local 0..7, 72..78
            int r = i / 34, c = i % 34;
            int row = (r < 8) ? r : (64 + r);
            zb[row * 34 + c] = 0ull;
        }
    }
    __syncthreads();

    // ---- phase 1: linears, raw streamed from global, outputs to smem ----
    {
        const int w    = tid >> 5, lane = tid & 31;
        const int mat  = w >> 2;                 // 0: left, 1: right
        const int kq   = w & 3,  k0 = kq * 16;
        const float* bias = mat ? br : bl;
        const float* rsrc = (mat ? Rb : Lb) + dg0 + 2 * lane;   // 8B-aligned pairs
        const ulonglong2* wt2 = reinterpret_cast<const ulonglong2*>(sm + OFF_C + mat * WT_SZ);

        u64 acc[8][2];
        #pragma unroll
        for (int kp = 0; kp < 8; ++kp) {
            u64 bp_ = pk2(__ldg(bias + k0 + 2 * kp), __ldg(bias + k0 + 2 * kp + 1));
            acc[kp][0] = bp_; acc[kp][1] = bp_;
        }
        #pragma unroll 4
        for (int l = 0; l < 64; ++l) {
            float2 rv = __ldg(reinterpret_cast<const float2*>(rsrc + l * 1024));
            u64 p0 = pk2(rv.x, rv.x), p1 = pk2(rv.y, rv.y);
            const ulonglong2* wl_ = wt2 + l * 17 + 4 * kq;
            #pragma unroll
            for (int i = 0; i < 4; ++i) {
                ulonglong2 ww = wl_[i];          // broadcast LDS.128 = 2 k-pairs
                fma2(acc[2 * i][0],     ww.x, p0);
                fma2(acc[2 * i][1],     ww.x, p1);
                fma2(acc[2 * i + 1][0], ww.y, p0);
                fma2(acc[2 * i + 1][1], ww.y, p1);
            }
        }
        // thread owns tile cols (2lane+1, 2lane+2)
        float* ost = sm + (mat ? (OFF_B + 8 * ST) : OFF_A) + 2 * lane + 1;
        #pragma unroll
        for (int kp = 0; kp < 8; ++kp) {
            float a0, b0_, a1, b1_;
            upk2(acc[kp][0], a0, b0_);           // col 2lane+1: k even, k odd
            upk2(acc[kp][1], a1, b1_);           // col 2lane+2
            ost[(k0 + 2 * kp) * ST + 0]     = a0;
            ost[(k0 + 2 * kp) * ST + 1]     = a1;
            ost[(k0 + 2 * kp + 1) * ST + 0] = b0_;
            ost[(k0 + 2 * kp + 1) * ST + 1] = b1_;
        }

        // tail cols (0,65) via H scratch: 2 mats x 64 k x 2 l-halves
        const int hmat = tid >> 7;
        const int hk   = (tid >> 1) & 63;
        const int lh   = tid & 1;
        const u64* Hp = reinterpret_cast<const u64*>(sm) + U64_H + hmat * 64;
        const float* wt = sm + OFF_C + hmat * WT_SZ + hk;
        const float* bias2 = hmat ? br : bl;
        u64 hacc = lh ? 0ull : pk2(__ldg(bias2 + hk), __ldg(bias2 + hk));
        #pragma unroll 8
        for (int t = 0; t < 32; ++t) {
            int l = 32 * lh + t;
            float wv = wt[l * ST];
            fma2(hacc, pk2(wv, wv), Hp[l]);      // lo: col0, hi: col65
        }
        float alo, ahi; upk2(hacc, alo, ahi);
        alo += __shfl_xor_sync(0xFFFFFFFFu, alo, 1);
        ahi += __shfl_xor_sync(0xFFFFFFFFu, ahi, 1);
        if (!lh) {
            float* tb = sm + (hmat ? (OFF_B + 8 * ST) : OFF_A) + hk * ST;
            tb[0]  = alo;
            tb[65] = ahi;
        }
    }
    __syncthreads();

    // ---- phase 2: correlation, triangular paired blocks (8-deep window) ----
    {
        const int cp = tid & 31;                  // col pair (2cp, 2cp+1)
        const int ig = tid >> 5;                  // 0..7
        const u64* ap = reinterpret_cast<const u64*>(sm) + cp;           // A row j at j*34
        const u64* bp = reinterpret_cast<const u64*>(sm) + U64_B + cp;   // orig row X at (X-56)*34
        u64* cst = reinterpret_cast<u64*>(sm) + U64_C + cp;
        const u64 keep = (dg0 == 0 && cp == 0) ? 0xFFFFFFFF00000000ull : ~0ull;

        #pragma unroll 1
        for (int blk = 0; blk < 2; ++blk) {
            const int i0  = blk ? (64 + 8 * ig) : (8 * ig);
            const int jlo = blk ? (8 * ig) : 0;
            const int nch = blk ? (8 - ig) : (ig + 1);
            u64 acc[8], win[8];
            #pragma unroll
            for (int q = 0; q < 8; ++q) acc[q] = 0ull;
            #pragma unroll
            for (int q = 1; q < 8; ++q) win[q] = bp[(jlo + 71 - i0 - q) * 34];
            #pragma unroll 1
            for (int ch = 0; ch < nch; ++ch) {
                const int j0 = jlo + ch * 8;
                u64 a2[8];
                #pragma unroll
                for (int t = 0; t < 8; ++t) a2[t] = ap[(j0 + t) * 34];
                #pragma unroll
                for (int t = 0; t < 8; ++t) {
                    u64 nv = bp[(j0 + t + 71 - i0) * 34];
                    fma2(acc[0], a2[t], nv);
                    #pragma unroll
                    for (int q = 1; q < 8; ++q) fma2(acc[q], a2[t], win[q]);
                    #pragma unroll
                    for (int q = 7; q > 1; --q) win[q] = win[q - 1];
                    win[1] = nv;
                }
            }
            #pragma unroll
            for (int q = 0; q < 8; ++q) cst[(i0 + q) * 34] = acc[q] & keep;
        }

        // tail cols (64,65): windowed j-range, stride-2 split per thread pair
        const int hi = tid >> 1;
        const int jh = tid & 1;
        const int tjlo = (hi > 63) ? (hi - 63) : 0;
        const int tjhi = (hi < 63) ? hi : 63;
        const u64* a2p = reinterpret_cast<const u64*>(sm) + 32;          // A halo word
        const u64* b2p = reinterpret_cast<const u64*>(sm) + U64_B + 32;  // B halo word
        u64 hacc = 0ull;
        #pragma unroll 4
        for (int j = tjlo + jh; j <= tjhi; j += 2)
            fma2(hacc, a2p[j * 34], b2p[(j + 71 - hi) * 34]);            // local rows 8..71
        float alo, ahi; upk2(hacc, alo, ahi);
        alo += __shfl_xor_sync(0xFFFFFFFFu, alo, 1);
        ahi += __shfl_xor_sync(0xFFFFFFFFu, ahi, 1);
        if (!jh) {
            u64 v = pk2(alo, ahi);
            if (dg0 == 960) v &= 0x00000000FFFFFFFFull;   // col 65 = d 1024 invalid
            reinterpret_cast<u64*>(sm)[U64_C + hi * 34 + 32] = v;
        }
    }

    // ---- phase 3: conv(128->64,k=3), 4d x 4k, warp spans 8 dq (halved d-span) ----
    const int w3 = tid >> 5, ln3 = tid & 31;
    const int dq = ((w3 & 1) << 3) | (ln3 & 7);   // 0..15
    const int kq = ((w3 >> 1) << 2) | (ln3 >> 3); // 0..15
    const int d0 = 4 * dq;
    u64 acc3[2][4];
    #pragma unroll
    for (int p = 0; p < 2; ++p)
        #pragma unroll
        for (int dd = 0; dd < 4; ++dd) acc3[p][dd] = 0ull;

    ulonglong2* wAs = reinterpret_cast<ulonglong2*>(sm);        // A region (dead)
    u64*        wBs = reinterpret_cast<u64*>(sm) + U64_B;       // B region (dead)
    #pragma unroll 1
    for (int s = 0; s < 4; ++s) {
        __syncthreads();   // corr written (s=0) / prev-stage weight reads done
        for (int i = tid; i < 1024; i += 256) {
            int kp = i >> 5, cl = i & 31;
            const float* s0 = Wconv + (2 * kp) * 384 + (32 * s + cl) * 3;
            ulonglong2 v;
            v.x = pk2(__ldg(s0 + 0), __ldg(s0 + 384));
            v.y = pk2(__ldg(s0 + 1), __ldg(s0 + 385));
            wAs[kp * 33 + cl] = v;
            wBs[kp * 33 + cl] = pk2(__ldg(s0 + 2), __ldg(s0 + 386));
        }
        __syncthreads();
        const float* cb = sm + OFF_C + (32 * s) * ST + d0;
        #pragma unroll 4
        for (int cl = 0; cl < 32; ++cl) {
            const float* crow = cb + cl * ST;
            ulonglong2 cA = *reinterpret_cast<const ulonglong2*>(crow);  // d0..d0+3
            float2     cC = *reinterpret_cast<const float2*>(crow + 4);  // d0+4, d0+5
            float f0, f1, f2, f3;
            upk2(cA.x, f0, f1); upk2(cA.y, f2, f3);
            u64 cv[6] = { pk2(f0, f0), pk2(f1, f1), pk2(f2, f2),
                          pk2(f3, f3), pk2(cC.x, cC.x), pk2(cC.y, cC.y) };
            #pragma unroll
            for (int p = 0; p < 2; ++p) {
                ulonglong2 wa = wAs[(2 * kq + p) * 33 + cl];
                u64        wb = wBs[(2 * kq + p) * 33 + cl];
                #pragma unroll
                for (int dd = 0; dd < 4; ++dd) {
                    fma2(acc3[p][dd], wa.x, cv[dd]);
                    fma2(acc3[p][dd], wa.y, cv[dd + 1]);
                    fma2(acc3[p][dd], wb,   cv[dd + 2]);
                }
            }
        }
    }

    float* ob = out + (size_t)b * 65536 + dg0 + d0;
    #pragma unroll
    for (int p = 0; p < 2; ++p) {
        float lo[4], hi[4];
        #pragma unroll
        for (int dd = 0; dd < 4; ++dd) upk2(acc3[p][dd], lo[dd], hi[dd]);
        float* o0 = ob + (size_t)(4 * kq + 2 * p) * Dc;
        *reinterpret_cast<float4*>(o0)      = make_float4(lo[0], lo[1], lo[2], lo[3]);
        *reinterpret_cast<float4*>(o0 + Dc) = make_float4(hi[0], hi[1], hi[2], hi[3]);
    }
}

extern "C" void kernel_launch(void* const* d_in, const int* in_sizes, int n_in,
                              void* d_out, int out_size)
{
    (void)in_sizes; (void)n_in; (void)out_size;
    const float* left  = (const float*)d_in[0];
    const float* right = (const float*)d_in[1];
    const float* Wl    = (const float*)d_in[2];
    const float* bl    = (const float*)d_in[3];
    const float* Wr    = (const float*)d_in[4];
    const float* br    = (const float*)d_in[5];
    const float* Wconv = (const float*)d_in[6];
    float* out = (float*)d_out;

    cudaFuncSetAttribute(cc_fused_kernel,
                         cudaFuncAttributeMaxDynamicSharedMemorySize, SMEM_BYTES);
    dim3 grid(Dc / 64, 256, 1);   // 4096 CTAs: one batch x 64-wide d-tile
    cc_fused_kernel<<<grid, 256, SMEM_BYTES>>>(left, right, Wl, bl, Wr, br, Wconv, out);
}